// round 11
// baseline (speedup 1.0000x reference)
#include <cuda_runtime.h>
#include <cuda_bf16.h>

#define BB 4
#define LL 1024
#define VV 1280
#define NE 768
#define NB 8
#define NH 32
#define NO 256          // NB*NH
#define NC 32           // chunks over L
#define CH 32           // chunk size (NC*CH == LL)

typedef unsigned long long ull;
typedef unsigned int u32;

// m16n8k16 row.col bf16 MMA, f32 accumulate-in-place
__device__ __forceinline__ void mma16816(float& d0, float& d1, float& d2, float& d3,
                                         uint4 a, uint2 b) {
    asm("mma.sync.aligned.m16n8k16.row.col.f32.bf16.bf16.f32 "
        "{%0,%1,%2,%3}, {%4,%5,%6,%7}, {%8,%9}, {%0,%1,%2,%3};"
        : "+f"(d0), "+f"(d1), "+f"(d2), "+f"(d3)
        : "r"(a.x), "r"(a.y), "r"(a.z), "r"(a.w), "r"(b.x), "r"(b.y));
}

// split a float2 into bf16x2 hi and lo words (x -> low half of word)
__device__ __forceinline__ void split2(float2 p, u32& hi, u32& lo) {
    __nv_bfloat162 hb = __float22bfloat162_rn(p);
    float2 hf = __bfloat1622float2(hb);
    float2 lf = make_float2(p.x - hf.x, p.y - hf.y);
    __nv_bfloat162 lb = __float22bfloat162_rn(lf);
    hi = *(u32*)&hb;
    lo = *(u32*)&lb;
}

// Scratch (device globals: no allocation allowed)
__device__ int   g_chunk_first[BB * NC * VV];
__device__ int   g_next[BB * NC * VV];
// fragment buffers
#define NMT 256   // m-tiles (4096/16)
#define NKT 16    // k(col)-tiles of x (256/16)
#define NKT1 48   // k-tiles over NE (768/16)
__device__ uint4 g_xah[NMT * NKT * 32];        // 2 MB  x A-frag hi
__device__ uint4 g_xal[NMT * NKT * 32];        // 2 MB  x A-frag lo
__device__ uint4 g_hah[NMT * NKT1 * 32];       // 6.3 MB h A-frag hi
__device__ uint4 g_hal[NMT * NKT1 * 32];       // 6.3 MB h A-frag lo
#define NV8 160   // 1280/8
__device__ uint2 g_wbh[NV8 * 2 * 32];          // W2 B-frag hi
__device__ uint2 g_wbl[NV8 * 2 * 32];          // W2 B-frag lo
#define N81 32    // 256/8
__device__ uint2 g_w1bh[N81 * NKT1 * 32];      // W1 B-frag hi
__device__ uint2 g_w1bl[N81 * NKT1 * 32];      // W1 B-frag lo

#define W1FRAG (N81 * NKT1 * 32)    // 49152
#define W2FRAG (NV8 * 2 * 32)       // 10240

// ---------------------------------------------------------------------------
// repack_h: h (f32, 4096x768) -> A-fragment hi/lo buffers (NKT1=48).
// ---------------------------------------------------------------------------
__global__ __launch_bounds__(256) void repack_h_kernel(const float* __restrict__ h)
{
    const int gt = blockIdx.x * 256 + threadIdx.x;    // 0..393215
    const int l = gt & 31;
    const int kt = (gt >> 5) % NKT1;
    const int mt = gt / (NKT1 * 32);
    const int g = l >> 2, t = l & 3;

    const int r0 = mt * 16 + g, r1 = r0 + 8;
    const int ca = kt * 16 + t * 2, cb = ca + 8;

    float2 p00 = *(const float2*)&h[r0 * NE + ca];
    float2 p10 = *(const float2*)&h[r1 * NE + ca];
    float2 p01 = *(const float2*)&h[r0 * NE + cb];
    float2 p11 = *(const float2*)&h[r1 * NE + cb];

    uint4 hv, lv;
    split2(p00, hv.x, lv.x);
    split2(p10, hv.y, lv.y);
    split2(p01, hv.z, lv.z);
    split2(p11, hv.w, lv.w);
    g_hah[gt] = hv;
    g_hal[gt] = lv;
}

// ---------------------------------------------------------------------------
// repack_w: W1[768,256] and W2[32,1280] -> B-fragment hi/lo buffers.
// One kernel (so gemm2_mma lands in the ncu capture slot).
// ---------------------------------------------------------------------------
__global__ __launch_bounds__(256) void repack_w_kernel(
    const float* __restrict__ W1, const float* __restrict__ W2)
{
    const int gt = blockIdx.x * 256 + threadIdx.x;
    const int l = gt & 31;
    const int g = l >> 2, t = l & 3;

    if (gt < W1FRAG) {
        const int kt = (gt >> 5) % NKT1;
        const int n8 = gt / (NKT1 * 32);
        const int o = n8 * 8 + g;
        const int k0 = kt * 16 + t * 2;

        float2 q0 = make_float2(W1[(k0 + 0) * NO + o], W1[(k0 + 1) * NO + o]);
        float2 q1 = make_float2(W1[(k0 + 8) * NO + o], W1[(k0 + 9) * NO + o]);

        uint2 hv, lv;
        split2(q0, hv.x, lv.x);
        split2(q1, hv.y, lv.y);
        g_w1bh[gt] = hv;
        g_w1bl[gt] = lv;
    } else {
        const int gw = gt - W1FRAG;
        if (gw >= W2FRAG) return;
        const int kt = (gw >> 5) & 1;
        const int v8 = gw >> 6;
        const int v = v8 * 8 + g;
        const int k0 = kt * 16 + t * 2;

        float2 q0 = make_float2(W2[(k0 + 0) * VV + v], W2[(k0 + 1) * VV + v]);
        float2 q1 = make_float2(W2[(k0 + 8) * VV + v], W2[(k0 + 9) * VV + v]);

        uint2 hv, lv;
        split2(q0, hv.x, lv.x);
        split2(q1, hv.y, lv.y);
        g_wbh[gw] = hv;
        g_wbl[gw] = lv;
    }
}

// ---------------------------------------------------------------------------
// GEMM1 on tensor cores: x = h @ W1, writing gemm2's A-fragments DIRECTLY.
// R11: 128 threads (4 warps), grid (4,64)=256 blocks (was 128) for occupancy.
// Warp = 2 m-tiles x 2 out-ktiles, register double-buffer prefetch (as R10).
// ---------------------------------------------------------------------------
__global__ __launch_bounds__(128) void gemm1_mma_kernel()
{
    const int w = threadIdx.x >> 5;     // 0..3
    const int l = threadIdx.x & 31;
    const int mw = w & 1;
    const int nw = w >> 1;
    const int mt0 = blockIdx.y * 4 + mw * 2;
    const int kto0 = blockIdx.x * 4 + nw * 2;
    const int n80 = kto0 * 2;

    float acc[2][4][4];
#pragma unroll
    for (int mi = 0; mi < 2; ++mi)
#pragma unroll
        for (int i = 0; i < 4; ++i)
#pragma unroll
            for (int q = 0; q < 4; ++q) acc[mi][i][q] = 0.0f;

    uint4 Ah[2][2], Al[2][2];   // [buf][mi]
    uint2 Bh[2][4], Bl[2][4];   // [buf][n8i]

#define LOAD_A(kt, buf) do { \
    _Pragma("unroll") \
    for (int mi = 0; mi < 2; ++mi) { \
        int idx = ((mt0 + mi) * NKT1 + (kt)) * 32 + l; \
        Ah[buf][mi] = g_hah[idx]; Al[buf][mi] = g_hal[idx]; \
    } } while (0)
#define LOAD_B(kt, buf) do { \
    _Pragma("unroll") \
    for (int i = 0; i < 4; ++i) { \
        int idx = ((n80 + i) * NKT1 + (kt)) * 32 + l; \
        Bh[buf][i] = g_w1bh[idx]; Bl[buf][i] = g_w1bl[idx]; \
    } } while (0)
#define DO_MMA(buf) do { \
    _Pragma("unroll") \
    for (int mi = 0; mi < 2; ++mi) \
    _Pragma("unroll") \
    for (int i = 0; i < 4; ++i) { \
        float* d = acc[mi][i]; \
        mma16816(d[0], d[1], d[2], d[3], Ah[buf][mi], Bh[buf][i]); \
        mma16816(d[0], d[1], d[2], d[3], Ah[buf][mi], Bl[buf][i]); \
        mma16816(d[0], d[1], d[2], d[3], Al[buf][mi], Bh[buf][i]); \
    } } while (0)

    LOAD_A(0, 0); LOAD_B(0, 0);
#pragma unroll 1
    for (int kt = 0; kt < NKT1; kt += 2) {
        LOAD_A(kt + 1, 1); LOAD_B(kt + 1, 1);
        DO_MMA(0);
        if (kt + 2 < NKT1) { LOAD_A(kt + 2, 0); LOAD_B(kt + 2, 0); }
        DO_MMA(1);
    }
#undef LOAD_A
#undef LOAD_B
#undef DO_MMA

    // epilogue: C-frags -> x A-frags (hi/lo)
#pragma unroll
    for (int mi = 0; mi < 2; ++mi)
#pragma unroll
        for (int kto = 0; kto < 2; ++kto) {
            const float* da = acc[mi][kto * 2 + 0];
            const float* db = acc[mi][kto * 2 + 1];
            uint4 hv, lv;
            split2(make_float2(da[0], da[1]), hv.x, lv.x);
            split2(make_float2(da[2], da[3]), hv.y, lv.y);
            split2(make_float2(db[0], db[1]), hv.z, lv.z);
            split2(make_float2(db[2], db[3]), hv.w, lv.w);
            int idx = ((mt0 + mi) * NKT + (kto0 + kto)) * 32 + l;
            g_xah[idx] = hv;
            g_xal[idx] = lv;
        }
}

// ---------------------------------------------------------------------------
// GEMM2 on tensor cores, software-pipelined (R11):
// flattened (bin, mi) loop of 16 iterations, A-frags double-buffered so the
// next iteration's loads overlap this iteration's 12 MMAs + stores.
// Per-iteration: 1 m-tile x 4 v8-tiles x 1 bin.
// ---------------------------------------------------------------------------
__global__ __launch_bounds__(128) void gemm2_mma_kernel(float* __restrict__ logits)
{
    const int w = threadIdx.x >> 5;
    const int l = threadIdx.x & 31;
    const int g = l >> 2, t = l & 3;
    const int bx = blockIdx.x;          // 0..39 : v block of 32
    const int by = blockIdx.y;          // 0..31 : m block of 128
    const int mtw = by * 8 + w * 2;     // warp's 2 m-tiles

    // B fragments hoisted for all 16 iterations
    uint2 Bh[4][2], Bl[4][2];
#pragma unroll
    for (int v8i = 0; v8i < 4; ++v8i)
#pragma unroll
        for (int j = 0; j < 2; ++j) {
            int idx = (((bx * 4 + v8i) * 2 + j) * 32) + l;
            Bh[v8i][j] = g_wbh[idx];
            Bl[v8i][j] = g_wbl[idx];
        }

    uint4 Ah[2][2], Al[2][2];           // [buf][j]
#pragma unroll
    for (int j = 0; j < 2; ++j) {       // it=0 : n=0, mi=0
        int idx = (mtw * NKT + j) * 32 + l;
        Ah[0][j] = g_xah[idx];
        Al[0][j] = g_xal[idx];
    }

#pragma unroll 1
    for (int it = 0; it < 16; ++it) {
        const int buf = it & 1;
        if (it < 15) {
            const int nn = (it + 1) >> 1;
            const int mm = (it + 1) & 1;
#pragma unroll
            for (int j = 0; j < 2; ++j) {
                int idx = ((mtw + mm) * NKT + 2 * nn + j) * 32 + l;
                Ah[buf ^ 1][j] = g_xah[idx];
                Al[buf ^ 1][j] = g_xal[idx];
            }
        }
        const int n = it >> 1;
        const int mi = it & 1;

        float acc[4][4];
#pragma unroll
        for (int v8i = 0; v8i < 4; ++v8i)
#pragma unroll
            for (int q = 0; q < 4; ++q) acc[v8i][q] = 0.0f;

#pragma unroll
        for (int v8i = 0; v8i < 4; ++v8i)
#pragma unroll
            for (int j = 0; j < 2; ++j) {
                float* d = acc[v8i];
                mma16816(d[0], d[1], d[2], d[3], Ah[buf][j], Bh[v8i][j]);
                mma16816(d[0], d[1], d[2], d[3], Ah[buf][j], Bl[v8i][j]);
                mma16816(d[0], d[1], d[2], d[3], Al[buf][j], Bh[v8i][j]);
            }

        const int mlo = (mtw + mi) * 16 + g;
#pragma unroll
        for (int v8i = 0; v8i < 4; ++v8i) {
            const int v = (bx * 4 + v8i) * 8 + t * 2;
            float* d = acc[v8i];
            *(float2*)&logits[((mlo + 0) * NB + n) * VV + v] = make_float2(d[0], d[1]);
            *(float2*)&logits[((mlo + 8) * NB + n) * VV + v] = make_float2(d[2], d[3]);
        }
    }
}

// ---------------------------------------------------------------------------
// Kernel A: per-chunk first occurrence. Block per (b, c); smem atomicMin.
// ---------------------------------------------------------------------------
__global__ __launch_bounds__(256) void first_occ_kernel(const int* __restrict__ targets)
{
    __shared__ int arr[VV];
    const int b = blockIdx.x >> 5;
    const int c = blockIdx.x & 31;
    const int tid = threadIdx.x;

#pragma unroll
    for (int it = 0; it < 5; ++it) arr[tid + it * 256] = LL;
    __syncthreads();
    if (tid < CH) {
        int j = c * CH + tid;
        atomicMin(&arr[targets[b * LL + j]], j);
    }
    __syncthreads();
#pragma unroll
    for (int it = 0; it < 5; ++it) {
        int idx = tid + it * 256;
        g_chunk_first[(b * NC + c) * VV + idx] = arr[idx];
    }
}

// ---------------------------------------------------------------------------
// Kernel B: exclusive suffix-min over chunks. One thread per (b, v).
// ---------------------------------------------------------------------------
__global__ __launch_bounds__(256) void suffix_kernel()
{
    const int gt = blockIdx.x * 256 + threadIdx.x;   // 0..5119
    const int b = gt / VV;
    const int v = gt - b * VV;

    int cf[NC];
#pragma unroll
    for (int c = 0; c < NC; ++c) cf[c] = g_chunk_first[(b * NC + c) * VV + v];

    int run = LL;
#pragma unroll
    for (int c = NC - 1; c >= 0; --c) {
        g_next[(b * NC + c) * VV + v] = run;
        run = min(run, cf[c]);
    }
}

// ---------------------------------------------------------------------------
// Kernel C: tte + censor mask. Block per (b, c, vhalf), 160 threads, 4 v each.
// ---------------------------------------------------------------------------
__global__ __launch_bounds__(160) void tte_mask_kernel(
    const int* __restrict__ targets,
    const float* __restrict__ age,
    const float* __restrict__ targets_age,
    float* __restrict__ out_tte,
    float* __restrict__ out_mask)
{
    __shared__ float ta_s[LL];
    __shared__ int ts[CH];
    __shared__ float ag[CH];

    const int b = blockIdx.x >> 6;
    const int rem = blockIdx.x & 63;
    const int c = rem >> 1;
    const int half = rem & 1;
    const int tid = threadIdx.x;        // 0..159

    for (int idx = tid; idx < LL; idx += 160)
        ta_s[idx] = targets_age[b * LL + idx];
    if (tid < CH) {
        int i = c * CH + tid;
        ts[tid] = targets[b * LL + i];
        ag[tid] = age[b * LL + i];
    }
    __syncthreads();

    const int vb = half * 640 + tid * 4;
    int4 c4 = *(const int4*)&g_next[(b * NC + c) * VV + vb];
    int cur0 = c4.x, cur1 = c4.y, cur2 = c4.z, cur3 = c4.w;

    for (int jj = CH - 1; jj >= 0; --jj) {
        const int i = c * CH + jj;
        const int t = ts[jj];
        const float ai = ag[jj];

        if (t == vb + 0) cur0 = i;
        if (t == vb + 1) cur1 = i;
        if (t == vb + 2) cur2 = i;
        if (t == vb + 3) cur3 = i;

        float tte[4];
        bool nev[4];
        int curs[4] = {cur0, cur1, cur2, cur3};
#pragma unroll
        for (int q = 0; q < 4; ++q) {
            int vv = vb + q;
            int idxr = curs[q];
            if (vv == 0 && i > 0) idxr = 0;  // reference's where(upper, targets, 0) quirk
            bool ne = (idxr == LL);
            int idx = ne ? (LL - 1) : idxr;
            tte[q] = ta_s[idx] - ai;
            nev[q] = ne;
        }

        const int row = b * LL + i;
        *(float4*)&out_tte[row * VV + vb] = make_float4(tte[0], tte[1], tte[2], tte[3]);

        int bin[4];
        bool valid[4];
#pragma unroll
        for (int q = 0; q < 4; ++q) {
            float tq = tte[q];
            valid[q] = (tq >= 0.0f) && (tq < 10.0f);
            bin[q] = (tq >= 1.25f) + (tq >= 2.5f) + (tq >= 3.75f) + (tq >= 5.0f)
                   + (tq >= 6.25f) + (tq >= 7.5f) + (tq >= 8.75f);
        }

        const int mbase = row * NB * VV + vb;
#pragma unroll
        for (int n = 0; n < 8; ++n) {
            float4 mv;
            mv.x = (nev[0] || (valid[0] && bin[0] == n)) ? 1.0f : 0.0f;
            mv.y = (nev[1] || (valid[1] && bin[1] == n)) ? 1.0f : 0.0f;
            mv.z = (nev[2] || (valid[2] && bin[2] == n)) ? 1.0f : 0.0f;
            mv.w = (nev[3] || (valid[3] && bin[3] == n)) ? 1.0f : 0.0f;
            *(float4*)&out_mask[mbase + n * VV] = mv;
        }
    }
}

// ---------------------------------------------------------------------------
extern "C" void kernel_launch(void* const* d_in, const int* in_sizes, int n_in,
                              void* d_out, int out_size)
{
    const float* h   = (const float*)d_in[0];  // (B,L,768) f32
    const float* age = (const float*)d_in[1];  // (B,L) f32
    const float* ta  = (const float*)d_in[2];  // (B,L) f32 targets_age
    // d_in[3] = delta_t (unused by outputs)
    const int*   tg  = (const int*)d_in[4];    // (B,L) i32 targets
    const float* W1  = (const float*)d_in[5];  // (768,256) f32
    const float* W2  = (const float*)d_in[6];  // (32,1280) f32

    float* out = (float*)d_out;
    float* out_logits = out;                                  // B*L*8*V
    float* out_tte    = out + (size_t)BB * LL * NB * VV;      // B*L*V
    float* out_mask   = out_tte + (size_t)BB * LL * VV;       // B*L*8*V

    // slot 4 (ncu capture) = gemm2_mma
    repack_w_kernel<<<(W1FRAG + W2FRAG + 255) / 256, 256>>>(W1, W2);
    repack_h_kernel<<<(NMT * NKT1 * 32) / 256, 256>>>(h);
    gemm1_mma_kernel<<<dim3(NKT / 4, NMT / 4), 128>>>();
    gemm2_mma_kernel<<<dim3(VV / 32, (BB * LL) / 128), 128>>>(out_logits);
    first_occ_kernel<<<BB * NC, 256>>>(tg);
    suffix_kernel<<<(BB * VV) / 256, 256>>>();
    tte_mask_kernel<<<BB * NC * 2, 160>>>(tg, age, ta, out_tte, out_mask);
}

// round 12
// speedup vs baseline: 1.1774x; 1.1774x over previous
#include <cuda_runtime.h>
#include <cuda_bf16.h>

#define BB 4
#define LL 1024
#define VV 1280
#define NE 768
#define NB 8
#define NH 32
#define NO 256          // NB*NH
#define NC 32           // chunks over L
#define CH 32           // chunk size (NC*CH == LL)

typedef unsigned long long ull;
typedef unsigned int u32;

// m16n8k16 row.col bf16 MMA, f32 accumulate-in-place
__device__ __forceinline__ void mma16816(float& d0, float& d1, float& d2, float& d3,
                                         uint4 a, uint2 b) {
    asm("mma.sync.aligned.m16n8k16.row.col.f32.bf16.bf16.f32 "
        "{%0,%1,%2,%3}, {%4,%5,%6,%7}, {%8,%9}, {%0,%1,%2,%3};"
        : "+f"(d0), "+f"(d1), "+f"(d2), "+f"(d3)
        : "r"(a.x), "r"(a.y), "r"(a.z), "r"(a.w), "r"(b.x), "r"(b.y));
}

// split a float2 into bf16x2 hi and lo words (x -> low half of word)
__device__ __forceinline__ void split2(float2 p, u32& hi, u32& lo) {
    __nv_bfloat162 hb = __float22bfloat162_rn(p);
    float2 hf = __bfloat1622float2(hb);
    float2 lf = make_float2(p.x - hf.x, p.y - hf.y);
    __nv_bfloat162 lb = __float22bfloat162_rn(lf);
    hi = *(u32*)&hb;
    lo = *(u32*)&lb;
}

// Scratch (device globals: no allocation allowed)
__device__ int   g_chunk_first[BB * NC * VV];
__device__ int   g_next[BB * NC * VV];
// fragment buffers
#define NMT 256   // m-tiles (4096/16)
#define NKT 16    // k(col)-tiles of x (256/16)
#define NKT1 48   // k-tiles over NE (768/16)
__device__ uint4 g_xah[NMT * NKT * 32];        // 2 MB  x A-frag hi
__device__ uint4 g_xal[NMT * NKT * 32];        // 2 MB  x A-frag lo
__device__ uint4 g_hah[NMT * NKT1 * 32];       // 6.3 MB h A-frag hi
__device__ uint4 g_hal[NMT * NKT1 * 32];       // 6.3 MB h A-frag lo
#define NV8 160   // 1280/8
__device__ uint2 g_wbh[NV8 * 2 * 32];          // W2 B-frag hi
__device__ uint2 g_wbl[NV8 * 2 * 32];          // W2 B-frag lo
#define N81 32    // 256/8
__device__ uint2 g_w1bh[N81 * NKT1 * 32];      // W1 B-frag hi
__device__ uint2 g_w1bl[N81 * NKT1 * 32];      // W1 B-frag lo

#define W1FRAG (N81 * NKT1 * 32)    // 49152
#define W2FRAG (NV8 * 2 * 32)       // 10240

// ---------------------------------------------------------------------------
// repack_h: h (f32, 4096x768) -> A-fragment hi/lo buffers (NKT1=48).
// ---------------------------------------------------------------------------
__global__ __launch_bounds__(256) void repack_h_kernel(const float* __restrict__ h)
{
    const int gt = blockIdx.x * 256 + threadIdx.x;    // 0..393215
    const int l = gt & 31;
    const int kt = (gt >> 5) % NKT1;
    const int mt = gt / (NKT1 * 32);
    const int g = l >> 2, t = l & 3;

    const int r0 = mt * 16 + g, r1 = r0 + 8;
    const int ca = kt * 16 + t * 2, cb = ca + 8;

    float2 p00 = *(const float2*)&h[r0 * NE + ca];
    float2 p10 = *(const float2*)&h[r1 * NE + ca];
    float2 p01 = *(const float2*)&h[r0 * NE + cb];
    float2 p11 = *(const float2*)&h[r1 * NE + cb];

    uint4 hv, lv;
    split2(p00, hv.x, lv.x);
    split2(p10, hv.y, lv.y);
    split2(p01, hv.z, lv.z);
    split2(p11, hv.w, lv.w);
    g_hah[gt] = hv;
    g_hal[gt] = lv;
}

// ---------------------------------------------------------------------------
// repack_w: W1[768,256] and W2[32,1280] -> B-fragment hi/lo buffers.
// ---------------------------------------------------------------------------
__global__ __launch_bounds__(256) void repack_w_kernel(
    const float* __restrict__ W1, const float* __restrict__ W2)
{
    const int gt = blockIdx.x * 256 + threadIdx.x;
    const int l = gt & 31;
    const int g = l >> 2, t = l & 3;

    if (gt < W1FRAG) {
        const int kt = (gt >> 5) % NKT1;
        const int n8 = gt / (NKT1 * 32);
        const int o = n8 * 8 + g;
        const int k0 = kt * 16 + t * 2;

        float2 q0 = make_float2(W1[(k0 + 0) * NO + o], W1[(k0 + 1) * NO + o]);
        float2 q1 = make_float2(W1[(k0 + 8) * NO + o], W1[(k0 + 9) * NO + o]);

        uint2 hv, lv;
        split2(q0, hv.x, lv.x);
        split2(q1, hv.y, lv.y);
        g_w1bh[gt] = hv;
        g_w1bl[gt] = lv;
    } else {
        const int gw = gt - W1FRAG;
        if (gw >= W2FRAG) return;
        const int kt = (gw >> 5) & 1;
        const int v8 = gw >> 6;
        const int v = v8 * 8 + g;
        const int k0 = kt * 16 + t * 2;

        float2 q0 = make_float2(W2[(k0 + 0) * VV + v], W2[(k0 + 1) * VV + v]);
        float2 q1 = make_float2(W2[(k0 + 8) * VV + v], W2[(k0 + 9) * VV + v]);

        uint2 hv, lv;
        split2(q0, hv.x, lv.x);
        split2(q1, hv.y, lv.y);
        g_wbh[gw] = hv;
        g_wbl[gw] = lv;
    }
}

// ---------------------------------------------------------------------------
// GEMM1 on tensor cores: x = h @ W1, writing gemm2's A-fragments DIRECTLY.
// 128 threads (4 warps), grid (4,64)=256 blocks (R11 regrid, kept).
// Warp = 2 m-tiles x 2 out-ktiles, register double-buffer prefetch (static buf).
// ---------------------------------------------------------------------------
__global__ __launch_bounds__(128) void gemm1_mma_kernel()
{
    const int w = threadIdx.x >> 5;     // 0..3
    const int l = threadIdx.x & 31;
    const int mw = w & 1;
    const int nw = w >> 1;
    const int mt0 = blockIdx.y * 4 + mw * 2;
    const int kto0 = blockIdx.x * 4 + nw * 2;
    const int n80 = kto0 * 2;

    float acc[2][4][4];
#pragma unroll
    for (int mi = 0; mi < 2; ++mi)
#pragma unroll
        for (int i = 0; i < 4; ++i)
#pragma unroll
            for (int q = 0; q < 4; ++q) acc[mi][i][q] = 0.0f;

    uint4 Ah[2][2], Al[2][2];   // [buf][mi]
    uint2 Bh[2][4], Bl[2][4];   // [buf][n8i]

#define LOAD_A(kt, buf) do { \
    _Pragma("unroll") \
    for (int mi = 0; mi < 2; ++mi) { \
        int idx = ((mt0 + mi) * NKT1 + (kt)) * 32 + l; \
        Ah[buf][mi] = g_hah[idx]; Al[buf][mi] = g_hal[idx]; \
    } } while (0)
#define LOAD_B(kt, buf) do { \
    _Pragma("unroll") \
    for (int i = 0; i < 4; ++i) { \
        int idx = ((n80 + i) * NKT1 + (kt)) * 32 + l; \
        Bh[buf][i] = g_w1bh[idx]; Bl[buf][i] = g_w1bl[idx]; \
    } } while (0)
#define DO_MMA(buf) do { \
    _Pragma("unroll") \
    for (int mi = 0; mi < 2; ++mi) \
    _Pragma("unroll") \
    for (int i = 0; i < 4; ++i) { \
        float* d = acc[mi][i]; \
        mma16816(d[0], d[1], d[2], d[3], Ah[buf][mi], Bh[buf][i]); \
        mma16816(d[0], d[1], d[2], d[3], Ah[buf][mi], Bl[buf][i]); \
        mma16816(d[0], d[1], d[2], d[3], Al[buf][mi], Bh[buf][i]); \
    } } while (0)

    LOAD_A(0, 0); LOAD_B(0, 0);
#pragma unroll 1
    for (int kt = 0; kt < NKT1; kt += 2) {
        LOAD_A(kt + 1, 1); LOAD_B(kt + 1, 1);
        DO_MMA(0);
        if (kt + 2 < NKT1) { LOAD_A(kt + 2, 0); LOAD_B(kt + 2, 0); }
        DO_MMA(1);
    }
#undef LOAD_A
#undef LOAD_B
#undef DO_MMA

    // epilogue: C-frags -> x A-frags (hi/lo)
#pragma unroll
    for (int mi = 0; mi < 2; ++mi)
#pragma unroll
        for (int kto = 0; kto < 2; ++kto) {
            const float* da = acc[mi][kto * 2 + 0];
            const float* db = acc[mi][kto * 2 + 1];
            uint4 hv, lv;
            split2(make_float2(da[0], da[1]), hv.x, lv.x);
            split2(make_float2(da[2], da[3]), hv.y, lv.y);
            split2(make_float2(db[0], db[1]), hv.z, lv.z);
            split2(make_float2(db[2], db[3]), hv.w, lv.w);
            int idx = ((mt0 + mi) * NKT + (kto0 + kto)) * 32 + l;
            g_xah[idx] = hv;
            g_xal[idx] = lv;
        }
}

// ---------------------------------------------------------------------------
// GEMM2 on tensor cores — R9 structure restored (verified 45us), with the
// bin loop FULLY UNROLLED so all fragment indices are compile-time constants
// and ptxas can hoist A-frag loads across bins (no dynamic register indexing).
// ---------------------------------------------------------------------------
__global__ __launch_bounds__(128) void gemm2_mma_kernel(float* __restrict__ logits)
{
    const int w = threadIdx.x >> 5;
    const int l = threadIdx.x & 31;
    const int g = l >> 2, t = l & 3;
    const int bx = blockIdx.x;          // 0..39 : v block of 32
    const int by = blockIdx.y;          // 0..31 : m block of 128
    const int mt0 = by * 8 + w * 2;

    uint2 Bh[4][2], Bl[4][2];
#pragma unroll
    for (int v8i = 0; v8i < 4; ++v8i)
#pragma unroll
        for (int j = 0; j < 2; ++j) {
            int idx = (((bx * 4 + v8i) * 2 + j) * 32) + l;
            Bh[v8i][j] = g_wbh[idx];
            Bl[v8i][j] = g_wbl[idx];
        }

#pragma unroll
    for (int n = 0; n < NB; ++n) {
        uint4 Ah[2][2], Al[2][2];
#pragma unroll
        for (int mi = 0; mi < 2; ++mi)
#pragma unroll
            for (int j = 0; j < 2; ++j) {
                int idx = (((mt0 + mi) * NKT + (2 * n + j)) * 32) + l;
                Ah[mi][j] = g_xah[idx];
                Al[mi][j] = g_xal[idx];
            }

        float acc[2][4][4];
#pragma unroll
        for (int mi = 0; mi < 2; ++mi)
#pragma unroll
            for (int v8i = 0; v8i < 4; ++v8i)
#pragma unroll
                for (int q = 0; q < 4; ++q) acc[mi][v8i][q] = 0.0f;

#pragma unroll
        for (int mi = 0; mi < 2; ++mi)
#pragma unroll
            for (int v8i = 0; v8i < 4; ++v8i)
#pragma unroll
                for (int j = 0; j < 2; ++j) {
                    float* d = acc[mi][v8i];
                    mma16816(d[0], d[1], d[2], d[3], Ah[mi][j], Bh[v8i][j]);
                    mma16816(d[0], d[1], d[2], d[3], Ah[mi][j], Bl[v8i][j]);
                    mma16816(d[0], d[1], d[2], d[3], Al[mi][j], Bh[v8i][j]);
                }

#pragma unroll
        for (int mi = 0; mi < 2; ++mi) {
            const int mlo = (mt0 + mi) * 16 + g;
#pragma unroll
            for (int v8i = 0; v8i < 4; ++v8i) {
                const int v = (bx * 4 + v8i) * 8 + t * 2;
                float* d = acc[mi][v8i];
                *(float2*)&logits[((mlo + 0) * NB + n) * VV + v] = make_float2(d[0], d[1]);
                *(float2*)&logits[((mlo + 8) * NB + n) * VV + v] = make_float2(d[2], d[3]);
            }
        }
    }
}

// ---------------------------------------------------------------------------
// Kernel A: per-chunk first occurrence. Block per (b, c); smem atomicMin.
// ---------------------------------------------------------------------------
__global__ __launch_bounds__(256) void first_occ_kernel(const int* __restrict__ targets)
{
    __shared__ int arr[VV];
    const int b = blockIdx.x >> 5;
    const int c = blockIdx.x & 31;
    const int tid = threadIdx.x;

#pragma unroll
    for (int it = 0; it < 5; ++it) arr[tid + it * 256] = LL;
    __syncthreads();
    if (tid < CH) {
        int j = c * CH + tid;
        atomicMin(&arr[targets[b * LL + j]], j);
    }
    __syncthreads();
#pragma unroll
    for (int it = 0; it < 5; ++it) {
        int idx = tid + it * 256;
        g_chunk_first[(b * NC + c) * VV + idx] = arr[idx];
    }
}

// ---------------------------------------------------------------------------
// Kernel B: exclusive suffix-min over chunks. One thread per (b, v).
// ---------------------------------------------------------------------------
__global__ __launch_bounds__(256) void suffix_kernel()
{
    const int gt = blockIdx.x * 256 + threadIdx.x;   // 0..5119
    const int b = gt / VV;
    const int v = gt - b * VV;

    int cf[NC];
#pragma unroll
    for (int c = 0; c < NC; ++c) cf[c] = g_chunk_first[(b * NC + c) * VV + v];

    int run = LL;
#pragma unroll
    for (int c = NC - 1; c >= 0; --c) {
        g_next[(b * NC + c) * VV + v] = run;
        run = min(run, cf[c]);
    }
}

// ---------------------------------------------------------------------------
// Kernel C: tte + censor mask. Block per (b, c, vhalf), 160 threads, 4 v each.
// ---------------------------------------------------------------------------
__global__ __launch_bounds__(160) void tte_mask_kernel(
    const int* __restrict__ targets,
    const float* __restrict__ age,
    const float* __restrict__ targets_age,
    float* __restrict__ out_tte,
    float* __restrict__ out_mask)
{
    __shared__ float ta_s[LL];
    __shared__ int ts[CH];
    __shared__ float ag[CH];

    const int b = blockIdx.x >> 6;
    const int rem = blockIdx.x & 63;
    const int c = rem >> 1;
    const int half = rem & 1;
    const int tid = threadIdx.x;        // 0..159

    for (int idx = tid; idx < LL; idx += 160)
        ta_s[idx] = targets_age[b * LL + idx];
    if (tid < CH) {
        int i = c * CH + tid;
        ts[tid] = targets[b * LL + i];
        ag[tid] = age[b * LL + i];
    }
    __syncthreads();

    const int vb = half * 640 + tid * 4;
    int4 c4 = *(const int4*)&g_next[(b * NC + c) * VV + vb];
    int cur0 = c4.x, cur1 = c4.y, cur2 = c4.z, cur3 = c4.w;

    for (int jj = CH - 1; jj >= 0; --jj) {
        const int i = c * CH + jj;
        const int t = ts[jj];
        const float ai = ag[jj];

        if (t == vb + 0) cur0 = i;
        if (t == vb + 1) cur1 = i;
        if (t == vb + 2) cur2 = i;
        if (t == vb + 3) cur3 = i;

        float tte[4];
        bool nev[4];
        int curs[4] = {cur0, cur1, cur2, cur3};
#pragma unroll
        for (int q = 0; q < 4; ++q) {
            int vv = vb + q;
            int idxr = curs[q];
            if (vv == 0 && i > 0) idxr = 0;  // reference's where(upper, targets, 0) quirk
            bool ne = (idxr == LL);
            int idx = ne ? (LL - 1) : idxr;
            tte[q] = ta_s[idx] - ai;
            nev[q] = ne;
        }

        const int row = b * LL + i;
        *(float4*)&out_tte[row * VV + vb] = make_float4(tte[0], tte[1], tte[2], tte[3]);

        int bin[4];
        bool valid[4];
#pragma unroll
        for (int q = 0; q < 4; ++q) {
            float tq = tte[q];
            valid[q] = (tq >= 0.0f) && (tq < 10.0f);
            bin[q] = (tq >= 1.25f) + (tq >= 2.5f) + (tq >= 3.75f) + (tq >= 5.0f)
                   + (tq >= 6.25f) + (tq >= 7.5f) + (tq >= 8.75f);
        }

        const int mbase = row * NB * VV + vb;
#pragma unroll
        for (int n = 0; n < 8; ++n) {
            float4 mv;
            mv.x = (nev[0] || (valid[0] && bin[0] == n)) ? 1.0f : 0.0f;
            mv.y = (nev[1] || (valid[1] && bin[1] == n)) ? 1.0f : 0.0f;
            mv.z = (nev[2] || (valid[2] && bin[2] == n)) ? 1.0f : 0.0f;
            mv.w = (nev[3] || (valid[3] && bin[3] == n)) ? 1.0f : 0.0f;
            *(float4*)&out_mask[mbase + n * VV] = mv;
        }
    }
}

// ---------------------------------------------------------------------------
extern "C" void kernel_launch(void* const* d_in, const int* in_sizes, int n_in,
                              void* d_out, int out_size)
{
    const float* h   = (const float*)d_in[0];  // (B,L,768) f32
    const float* age = (const float*)d_in[1];  // (B,L) f32
    const float* ta  = (const float*)d_in[2];  // (B,L) f32 targets_age
    // d_in[3] = delta_t (unused by outputs)
    const int*   tg  = (const int*)d_in[4];    // (B,L) i32 targets
    const float* W1  = (const float*)d_in[5];  // (768,256) f32
    const float* W2  = (const float*)d_in[6];  // (32,1280) f32

    float* out = (float*)d_out;
    float* out_logits = out;                                  // B*L*8*V
    float* out_tte    = out + (size_t)BB * LL * NB * VV;      // B*L*V
    float* out_mask   = out_tte + (size_t)BB * LL * VV;       // B*L*8*V

    // slot 4 (ncu capture) = gemm2_mma
    repack_w_kernel<<<(W1FRAG + W2FRAG + 255) / 256, 256>>>(W1, W2);
    repack_h_kernel<<<(NMT * NKT1 * 32) / 256, 256>>>(h);
    gemm1_mma_kernel<<<dim3(NKT / 4, NMT / 4), 128>>>();
    gemm2_mma_kernel<<<dim3(VV / 32, (BB * LL) / 128), 128>>>(out_logits);
    first_occ_kernel<<<BB * NC, 256>>>(tg);
    suffix_kernel<<<(BB * VV) / 256, 256>>>();
    tte_mask_kernel<<<BB * NC * 2, 160>>>(tg, age, ta, out_tte, out_mask);
}

// round 13
// speedup vs baseline: 1.2074x; 1.0255x over previous
#include <cuda_runtime.h>
#include <cuda_bf16.h>

#define BB 4
#define LL 1024
#define VV 1280
#define NE 768
#define NB 8
#define NH 32
#define NO 256          // NB*NH
#define NC 32           // chunks over L
#define CH 32           // chunk size (NC*CH == LL)

typedef unsigned long long ull;
typedef unsigned int u32;

// m16n8k16 row.col bf16 MMA, f32 accumulate-in-place
__device__ __forceinline__ void mma16816(float& d0, float& d1, float& d2, float& d3,
                                         uint4 a, uint2 b) {
    asm("mma.sync.aligned.m16n8k16.row.col.f32.bf16.bf16.f32 "
        "{%0,%1,%2,%3}, {%4,%5,%6,%7}, {%8,%9}, {%0,%1,%2,%3};"
        : "+f"(d0), "+f"(d1), "+f"(d2), "+f"(d3)
        : "r"(a.x), "r"(a.y), "r"(a.z), "r"(a.w), "r"(b.x), "r"(b.y));
}

// split a float2 into bf16x2 hi and lo words
__device__ __forceinline__ void split2(float2 p, u32& hi, u32& lo) {
    __nv_bfloat162 hb = __float22bfloat162_rn(p);
    float2 hf = __bfloat1622float2(hb);
    float2 lf = make_float2(p.x - hf.x, p.y - hf.y);
    __nv_bfloat162 lb = __float22bfloat162_rn(lf);
    hi = *(u32*)&hb;
    lo = *(u32*)&lb;
}

// Scratch (device globals: no allocation allowed)
__device__ int   g_chunk_first[BB * NC * VV];
__device__ int   g_next[BB * NC * VV];
// fragment buffers
#define NMT 256   // m-tiles (4096/16)
#define NKT 16    // k(col)-tiles of x (256/16)
#define NKT1 48   // k-tiles over NE (768/16)
__device__ uint4 g_xah[NMT * NKT * 32];
__device__ uint4 g_xal[NMT * NKT * 32];
__device__ uint4 g_hah[NMT * NKT1 * 32];
__device__ uint4 g_hal[NMT * NKT1 * 32];
#define NV8 160   // 1280/8
__device__ uint2 g_wbh[NV8 * 2 * 32];
__device__ uint2 g_wbl[NV8 * 2 * 32];
#define N81 32    // 256/8
__device__ uint2 g_w1bh[N81 * NKT1 * 32];
__device__ uint2 g_w1bl[N81 * NKT1 * 32];

#define W1FRAG (N81 * NKT1 * 32)    // 49152
#define W2FRAG (NV8 * 2 * 32)       // 10240
#define NWBLK  ((W1FRAG + W2FRAG + 255) / 256)   // 232
#define NHBLK  ((NMT * NKT1 * 32) / 256)          // 1536
#define NFOBLK (BB * NC)                           // 128

// ===========================================================================
// FUSED PREP: repack_w + repack_h + first_occ   (256 threads)
// ===========================================================================
__global__ __launch_bounds__(256) void fused_prep_kernel(
    const float* __restrict__ W1, const float* __restrict__ W2,
    const float* __restrict__ h, const int* __restrict__ targets)
{
    __shared__ int arr[VV];
    const int blk = blockIdx.x;
    const int tid = threadIdx.x;

    if (blk < NWBLK) {
        // ---- repack_w (byte-identical body) ----
        const int gt = blk * 256 + tid;
        const int l = gt & 31;
        const int g = l >> 2, t = l & 3;

        if (gt < W1FRAG) {
            const int kt = (gt >> 5) % NKT1;
            const int n8 = gt / (NKT1 * 32);
            const int o = n8 * 8 + g;
            const int k0 = kt * 16 + t * 2;

            float2 q0 = make_float2(W1[(k0 + 0) * NO + o], W1[(k0 + 1) * NO + o]);
            float2 q1 = make_float2(W1[(k0 + 8) * NO + o], W1[(k0 + 9) * NO + o]);

            uint2 hv, lv;
            split2(q0, hv.x, lv.x);
            split2(q1, hv.y, lv.y);
            g_w1bh[gt] = hv;
            g_w1bl[gt] = lv;
        } else {
            const int gw = gt - W1FRAG;
            if (gw >= W2FRAG) return;
            const int kt = (gw >> 5) & 1;
            const int v8 = gw >> 6;
            const int v = v8 * 8 + g;
            const int k0 = kt * 16 + t * 2;

            float2 q0 = make_float2(W2[(k0 + 0) * VV + v], W2[(k0 + 1) * VV + v]);
            float2 q1 = make_float2(W2[(k0 + 8) * VV + v], W2[(k0 + 9) * VV + v]);

            uint2 hv, lv;
            split2(q0, hv.x, lv.x);
            split2(q1, hv.y, lv.y);
            g_wbh[gw] = hv;
            g_wbl[gw] = lv;
        }
    } else if (blk < NWBLK + NHBLK) {
        // ---- repack_h (byte-identical body) ----
        const int gt = (blk - NWBLK) * 256 + tid;
        const int l = gt & 31;
        const int kt = (gt >> 5) % NKT1;
        const int mt = gt / (NKT1 * 32);
        const int g = l >> 2, t = l & 3;

        const int r0 = mt * 16 + g, r1 = r0 + 8;
        const int ca = kt * 16 + t * 2, cb = ca + 8;

        float2 p00 = *(const float2*)&h[r0 * NE + ca];
        float2 p10 = *(const float2*)&h[r1 * NE + ca];
        float2 p01 = *(const float2*)&h[r0 * NE + cb];
        float2 p11 = *(const float2*)&h[r1 * NE + cb];

        uint4 hv, lv;
        split2(p00, hv.x, lv.x);
        split2(p10, hv.y, lv.y);
        split2(p01, hv.z, lv.z);
        split2(p11, hv.w, lv.w);
        g_hah[gt] = hv;
        g_hal[gt] = lv;
    } else {
        // ---- first_occ (byte-identical body) ----
        const int fb = blk - NWBLK - NHBLK;
        const int b = fb >> 5;
        const int c = fb & 31;

#pragma unroll
        for (int it = 0; it < 5; ++it) arr[tid + it * 256] = LL;
        __syncthreads();
        if (tid < CH) {
            int j = c * CH + tid;
            atomicMin(&arr[targets[b * LL + j]], j);
        }
        __syncthreads();
#pragma unroll
        for (int it = 0; it < 5; ++it) {
            int idx = tid + it * 256;
            g_chunk_first[(b * NC + c) * VV + idx] = arr[idx];
        }
    }
}

// ===========================================================================
// FUSED MID: gemm1_mma (256 blocks) + suffix (40 blocks)   (128 threads)
// ===========================================================================
__global__ __launch_bounds__(128) void fused_mid_kernel()
{
    const int blk = blockIdx.x;

    if (blk < 256) {
        // ---- gemm1_mma (byte-identical body; bx=blk&3, by=blk>>2) ----
        const int w = threadIdx.x >> 5;
        const int l = threadIdx.x & 31;
        const int mw = w & 1;
        const int nw = w >> 1;
        const int mt0 = (blk >> 2) * 4 + mw * 2;
        const int kto0 = (blk & 3) * 4 + nw * 2;
        const int n80 = kto0 * 2;

        float acc[2][4][4];
#pragma unroll
        for (int mi = 0; mi < 2; ++mi)
#pragma unroll
            for (int i = 0; i < 4; ++i)
#pragma unroll
                for (int q = 0; q < 4; ++q) acc[mi][i][q] = 0.0f;

        uint4 Ah[2][2], Al[2][2];
        uint2 Bh[2][4], Bl[2][4];

#define LOAD_A(kt, buf) do { \
    _Pragma("unroll") \
    for (int mi = 0; mi < 2; ++mi) { \
        int idx = ((mt0 + mi) * NKT1 + (kt)) * 32 + l; \
        Ah[buf][mi] = g_hah[idx]; Al[buf][mi] = g_hal[idx]; \
    } } while (0)
#define LOAD_B(kt, buf) do { \
    _Pragma("unroll") \
    for (int i = 0; i < 4; ++i) { \
        int idx = ((n80 + i) * NKT1 + (kt)) * 32 + l; \
        Bh[buf][i] = g_w1bh[idx]; Bl[buf][i] = g_w1bl[idx]; \
    } } while (0)
#define DO_MMA(buf) do { \
    _Pragma("unroll") \
    for (int mi = 0; mi < 2; ++mi) \
    _Pragma("unroll") \
    for (int i = 0; i < 4; ++i) { \
        float* d = acc[mi][i]; \
        mma16816(d[0], d[1], d[2], d[3], Ah[buf][mi], Bh[buf][i]); \
        mma16816(d[0], d[1], d[2], d[3], Ah[buf][mi], Bl[buf][i]); \
        mma16816(d[0], d[1], d[2], d[3], Al[buf][mi], Bh[buf][i]); \
    } } while (0)

        LOAD_A(0, 0); LOAD_B(0, 0);
#pragma unroll 1
        for (int kt = 0; kt < NKT1; kt += 2) {
            LOAD_A(kt + 1, 1); LOAD_B(kt + 1, 1);
            DO_MMA(0);
            if (kt + 2 < NKT1) { LOAD_A(kt + 2, 0); LOAD_B(kt + 2, 0); }
            DO_MMA(1);
        }
#undef LOAD_A
#undef LOAD_B
#undef DO_MMA

#pragma unroll
        for (int mi = 0; mi < 2; ++mi)
#pragma unroll
            for (int kto = 0; kto < 2; ++kto) {
                const float* da = acc[mi][kto * 2 + 0];
                const float* db = acc[mi][kto * 2 + 1];
                uint4 hv, lv;
                split2(make_float2(da[0], da[1]), hv.x, lv.x);
                split2(make_float2(da[2], da[3]), hv.y, lv.y);
                split2(make_float2(db[0], db[1]), hv.z, lv.z);
                split2(make_float2(db[2], db[3]), hv.w, lv.w);
                int idx = ((mt0 + mi) * NKT + (kto0 + kto)) * 32 + l;
                g_xah[idx] = hv;
                g_xal[idx] = lv;
            }
    } else {
        // ---- suffix (body identical; 128-thread blocks) ----
        const int gt = (blk - 256) * 128 + threadIdx.x;   // 0..5119
        if (gt >= BB * VV) return;
        const int b = gt / VV;
        const int v = gt - b * VV;

        int cf[NC];
#pragma unroll
        for (int c = 0; c < NC; ++c) cf[c] = g_chunk_first[(b * NC + c) * VV + v];

        int run = LL;
#pragma unroll
        for (int c = NC - 1; c >= 0; --c) {
            g_next[(b * NC + c) * VV + v] = run;
            run = min(run, cf[c]);
        }
    }
}

// ===========================================================================
// FUSED MAIN: gemm2_mma (1280 blocks) + tte_mask (256 blocks), interleaved
// every 6th block = tte_mask.   (160 threads; gemm2 uses tid<128)
// ===========================================================================
__global__ __launch_bounds__(160) void fused_main_kernel(
    const int* __restrict__ targets,
    const float* __restrict__ age,
    const float* __restrict__ targets_age,
    float* __restrict__ logits,
    float* __restrict__ out_tte,
    float* __restrict__ out_mask)
{
    __shared__ float ta_s[LL];
    __shared__ int ts[CH];
    __shared__ float ag[CH];

    const int blk = blockIdx.x;          // 0..1535
    const int tq = blk / 6;
    const int rq = blk - tq * 6;

    if (rq != 0) {
        // ---- gemm2_mma (byte-identical body); idx = tq*5 + rq-1 ----
        if (threadIdx.x >= 128) return;
        const int idx2 = tq * 5 + (rq - 1);   // 0..1279
        const int bx = idx2 % 40;
        const int by = idx2 / 40;

        const int w = threadIdx.x >> 5;
        const int l = threadIdx.x & 31;
        const int g = l >> 2, t = l & 3;
        const int mt0 = by * 8 + w * 2;

        uint2 Bh[4][2], Bl[4][2];
#pragma unroll
        for (int v8i = 0; v8i < 4; ++v8i)
#pragma unroll
            for (int j = 0; j < 2; ++j) {
                int idx = (((bx * 4 + v8i) * 2 + j) * 32) + l;
                Bh[v8i][j] = g_wbh[idx];
                Bl[v8i][j] = g_wbl[idx];
            }

#pragma unroll
        for (int n = 0; n < NB; ++n) {
            uint4 Ah[2][2], Al[2][2];
#pragma unroll
            for (int mi = 0; mi < 2; ++mi)
#pragma unroll
                for (int j = 0; j < 2; ++j) {
                    int idx = (((mt0 + mi) * NKT + (2 * n + j)) * 32) + l;
                    Ah[mi][j] = g_xah[idx];
                    Al[mi][j] = g_xal[idx];
                }

            float acc[2][4][4];
#pragma unroll
            for (int mi = 0; mi < 2; ++mi)
#pragma unroll
                for (int v8i = 0; v8i < 4; ++v8i)
#pragma unroll
                    for (int q = 0; q < 4; ++q) acc[mi][v8i][q] = 0.0f;

#pragma unroll
            for (int mi = 0; mi < 2; ++mi)
#pragma unroll
                for (int v8i = 0; v8i < 4; ++v8i)
#pragma unroll
                    for (int j = 0; j < 2; ++j) {
                        float* d = acc[mi][v8i];
                        mma16816(d[0], d[1], d[2], d[3], Ah[mi][j], Bh[v8i][j]);
                        mma16816(d[0], d[1], d[2], d[3], Ah[mi][j], Bl[v8i][j]);
                        mma16816(d[0], d[1], d[2], d[3], Al[mi][j], Bh[v8i][j]);
                    }

#pragma unroll
            for (int mi = 0; mi < 2; ++mi) {
                const int mlo = (mt0 + mi) * 16 + g;
#pragma unroll
                for (int v8i = 0; v8i < 4; ++v8i) {
                    const int v = (bx * 4 + v8i) * 8 + t * 2;
                    float* d = acc[mi][v8i];
                    *(float2*)&logits[((mlo + 0) * NB + n) * VV + v] = make_float2(d[0], d[1]);
                    *(float2*)&logits[((mlo + 8) * NB + n) * VV + v] = make_float2(d[2], d[3]);
                }
            }
        }
    } else {
        // ---- tte_mask (byte-identical body); block index = tq (0..255) ----
        const int b = tq >> 6;
        const int rem = tq & 63;
        const int c = rem >> 1;
        const int half = rem & 1;
        const int tid = threadIdx.x;        // 0..159

        for (int idx = tid; idx < LL; idx += 160)
            ta_s[idx] = targets_age[b * LL + idx];
        if (tid < CH) {
            int i = c * CH + tid;
            ts[tid] = targets[b * LL + i];
            ag[tid] = age[b * LL + i];
        }
        __syncthreads();

        const int vb = half * 640 + tid * 4;
        int4 c4 = *(const int4*)&g_next[(b * NC + c) * VV + vb];
        int cur0 = c4.x, cur1 = c4.y, cur2 = c4.z, cur3 = c4.w;

        for (int jj = CH - 1; jj >= 0; --jj) {
            const int i = c * CH + jj;
            const int t = ts[jj];
            const float ai = ag[jj];

            if (t == vb + 0) cur0 = i;
            if (t == vb + 1) cur1 = i;
            if (t == vb + 2) cur2 = i;
            if (t == vb + 3) cur3 = i;

            float tte[4];
            bool nev[4];
            int curs[4] = {cur0, cur1, cur2, cur3};
#pragma unroll
            for (int q = 0; q < 4; ++q) {
                int vv = vb + q;
                int idxr = curs[q];
                if (vv == 0 && i > 0) idxr = 0;  // reference's where(upper,...) quirk
                bool ne = (idxr == LL);
                int idx = ne ? (LL - 1) : idxr;
                tte[q] = ta_s[idx] - ai;
                nev[q] = ne;
            }

            const int row = b * LL + i;
            *(float4*)&out_tte[row * VV + vb] = make_float4(tte[0], tte[1], tte[2], tte[3]);

            int bin[4];
            bool valid[4];
#pragma unroll
            for (int q = 0; q < 4; ++q) {
                float tq2 = tte[q];
                valid[q] = (tq2 >= 0.0f) && (tq2 < 10.0f);
                bin[q] = (tq2 >= 1.25f) + (tq2 >= 2.5f) + (tq2 >= 3.75f) + (tq2 >= 5.0f)
                       + (tq2 >= 6.25f) + (tq2 >= 7.5f) + (tq2 >= 8.75f);
            }

            const int mbase = row * NB * VV + vb;
#pragma unroll
            for (int n = 0; n < 8; ++n) {
                float4 mv;
                mv.x = (nev[0] || (valid[0] && bin[0] == n)) ? 1.0f : 0.0f;
                mv.y = (nev[1] || (valid[1] && bin[1] == n)) ? 1.0f : 0.0f;
                mv.z = (nev[2] || (valid[2] && bin[2] == n)) ? 1.0f : 0.0f;
                mv.w = (nev[3] || (valid[3] && bin[3] == n)) ? 1.0f : 0.0f;
                *(float4*)&out_mask[mbase + n * VV] = mv;
            }
        }
    }
}

// ---------------------------------------------------------------------------
extern "C" void kernel_launch(void* const* d_in, const int* in_sizes, int n_in,
                              void* d_out, int out_size)
{
    const float* h   = (const float*)d_in[0];  // (B,L,768) f32
    const float* age = (const float*)d_in[1];  // (B,L) f32
    const float* ta  = (const float*)d_in[2];  // (B,L) f32 targets_age
    // d_in[3] = delta_t (unused by outputs)
    const int*   tg  = (const int*)d_in[4];    // (B,L) i32 targets
    const float* W1  = (const float*)d_in[5];  // (768,256) f32
    const float* W2  = (const float*)d_in[6];  // (32,1280) f32

    float* out = (float*)d_out;
    float* out_logits = out;                                  // B*L*8*V
    float* out_tte    = out + (size_t)BB * LL * NB * VV;      // B*L*V
    float* out_mask   = out_tte + (size_t)BB * LL * VV;       // B*L*8*V

    fused_prep_kernel<<<NWBLK + NHBLK + NFOBLK, 256>>>(W1, W2, h, tg);
    fused_mid_kernel<<<256 + 40, 128>>>();
    fused_main_kernel<<<1536, 160>>>(tg, age, ta, out_logits, out_tte, out_mask);
}